// round 1
// baseline (speedup 1.0000x reference)
#include <cuda_runtime.h>
#include <math.h>

#define DD   768
#define MAXK 150
#define MAXN 1500
#define MAXB 256
#define MAXM 256
#define BETA_C 0.1f

// ---- scratch (static device globals; no allocation) ----
__device__ float g_R[(size_t)MAXK * DD * DD];      // 354 MB rotate matrices
__device__ float g_c2[MAXN];                        // centroid squared norms
__device__ float g_dotin[MAXB * MAXN];              // pooled . cent^T
__device__ float g_dotood[MAXM * MAXN];             // ood    . cent^T
__device__ int   g_cnt[MAXK];                       // balls per class
__device__ int   g_clist[MAXK * MAXN];              // class -> ball list
__device__ int   g_ballin[MAXB];                    // nearest same-class ball
__device__ float g_din[MAXB];
__device__ int   g_near[MAXK * MAXM];               // nearest class-k ball per ood sample
__device__ float g_dnear[MAXK * MAXM];
__device__ float g_euc2ood[MAXK * MAXM];            // accumulated ||R(o-c)||^2
__device__ float g_eucin2[MAXB];

// ---------------------------------------------------------------------------
__global__ void abl_zero_cnt(int K) {
    int t = threadIdx.x;
    if (t < K) g_cnt[t] = 0;
}

__global__ void abl_zero_euc2(int total) {
    int i = blockIdx.x * blockDim.x + threadIdx.x;
    if (i < total) g_euc2ood[i] = 0.f;
}

__global__ void abl_fill_clist(const int* __restrict__ blab, int N) {
    int n = blockIdx.x * blockDim.x + threadIdx.x;
    if (n >= N) return;
    int k = blab[n];
    int pos = atomicAdd(&g_cnt[k], 1);
    g_clist[k * MAXN + pos] = n;
}

// ---------------------------------------------------------------------------
// Build R[k] from packed L (strict lower), U (strict upper via transpose), Dd.
// 32x32 tiles over the lower-incl-diag triangle; transpose staged in smem so
// both the L-side and U-side global writes are coalesced.
__global__ void abl_build_R(const float* __restrict__ L, const float* __restrict__ U,
                            const float* __restrict__ Ddm, int NTRI) {
    int k = blockIdx.y;
    int tidx = blockIdx.x;
    int ti = 0;
    while ((ti + 1) * (ti + 2) / 2 <= tidx) ti++;
    int tj = tidx - ti * (ti + 1) / 2;

    const float* Lk = L + (size_t)k * NTRI;
    const float* Uk = U + (size_t)k * NTRI;
    float* Rk = g_R + (size_t)k * DD * DD;

    __shared__ float su[32][33];
    int tx = threadIdx.x & 31, ty = threadIdx.x >> 5;

#pragma unroll
    for (int s = 0; s < 4; s++) {
        int ry = ty + 8 * s;
        int r = ti * 32 + ry, c = tj * 32 + tx;
        if (r > c) {
            size_t p = (size_t)r * (r - 1) / 2 + c;
            Rk[(size_t)r * DD + c] = Lk[p];
            su[ry][tx] = Uk[p];
        } else if (r == c) {
            Rk[(size_t)r * DD + c] = Ddm[(size_t)k * DD + r];
        }
    }
    __syncthreads();
#pragma unroll
    for (int s = 0; s < 4; s++) {
        int ry = ty + 8 * s;
        int ro = tj * 32 + ry, co = ti * 32 + tx;   // R[ro][co] = U_packed(co, ro)
        if (co > ro) Rk[(size_t)ro * DD + co] = su[tx][ry];
    }
}

// ---------------------------------------------------------------------------
// centroid squared norms
__global__ void abl_c2(const float* __restrict__ cent) {
    int n = blockIdx.x;
    __shared__ float sr[128];
    float s = 0.f;
    for (int j = threadIdx.x; j < DD; j += 128) {
        float v = cent[(size_t)n * DD + j];
        s += v * v;
    }
    sr[threadIdx.x] = s;
    __syncthreads();
    for (int k = 64; k > 0; k >>= 1) {
        if (threadIdx.x < k) sr[threadIdx.x] += sr[threadIdx.x + k];
        __syncthreads();
    }
    if (threadIdx.x == 0) g_c2[n] = sr[0];
}

// ---------------------------------------------------------------------------
// C[m][n] = A[m,:].B[n,:]  (NT).  64x64 tiles, 16x16 threads, 4x4 microtile.
__global__ __launch_bounds__(256) void abl_dot_nt(const float* __restrict__ A,
                                                  const float* __restrict__ Bm,
                                                  int Ma, int Nb, int which) {
    float* C = which ? g_dotood : g_dotin;
    __shared__ float sA[16][65];
    __shared__ float sB[16][65];
    int n0 = blockIdx.x * 64, m0 = blockIdx.y * 64;
    int t = threadIdx.x, tx = t & 15, ty = t >> 4;
    float acc[4][4];
#pragma unroll
    for (int r = 0; r < 4; r++)
#pragma unroll
        for (int c = 0; c < 4; c++) acc[r][c] = 0.f;

    for (int j0 = 0; j0 < DD; j0 += 16) {
#pragma unroll
        for (int e = 0; e < 4; e++) {
            int mm = (t >> 4) + 16 * e;
            int m = m0 + mm;
            sA[tx][mm] = (m < Ma) ? A[(size_t)m * DD + j0 + tx] : 0.f;
        }
#pragma unroll
        for (int e = 0; e < 4; e++) {
            int nn = (t >> 4) + 16 * e;
            int n = n0 + nn;
            sB[tx][nn] = (n < Nb) ? Bm[(size_t)n * DD + j0 + tx] : 0.f;
        }
        __syncthreads();
#pragma unroll
        for (int kk = 0; kk < 16; kk++) {
            float a[4], b[4];
#pragma unroll
            for (int r = 0; r < 4; r++) a[r] = sA[kk][ty * 4 + r];
#pragma unroll
            for (int c = 0; c < 4; c++) b[c] = sB[kk][tx * 4 + c];
#pragma unroll
            for (int r = 0; r < 4; r++)
#pragma unroll
                for (int c = 0; c < 4; c++) acc[r][c] += a[r] * b[c];
        }
        __syncthreads();
    }
#pragma unroll
    for (int r = 0; r < 4; r++) {
        int m = m0 + ty * 4 + r;
        if (m >= Ma) continue;
#pragma unroll
        for (int c = 0; c < 4; c++) {
            int n = n0 + tx * 4 + c;
            if (n < Nb) C[(size_t)m * Nb + n] = acc[r][c];
        }
    }
}

// ---------------------------------------------------------------------------
// nearest same-class ball per in-dist sample (argmin of ||c||^2 - 2 a.c)
__global__ void abl_assign_in(const int* __restrict__ labels,
                              const float* __restrict__ delta, int B, int N) {
    int b = blockIdx.x * blockDim.x + threadIdx.x;
    if (b >= B) return;
    int lab = labels[b];
    int cnt = g_cnt[lab];
    float best = 3.4e38f;
    int bi = 0;
    for (int i = 0; i < cnt; i++) {
        int n = g_clist[lab * MAXN + i];
        float s = g_c2[n] - 2.f * g_dotin[(size_t)b * N + n];
        if (s < best) { best = s; bi = n; }
    }
    g_ballin[b] = bi;
    g_din[b] = delta[bi];
}

// nearest class-k ball per ood sample
__global__ void abl_nearest_ood(const float* __restrict__ delta, int M, int N) {
    int k = blockIdx.x;
    int cnt = g_cnt[k];
    for (int m = threadIdx.x; m < M; m += blockDim.x) {
        float best = 3.4e38f;
        int bi = 0;
        for (int i = 0; i < cnt; i++) {
            int n = g_clist[k * MAXN + i];
            float s = g_c2[n] - 2.f * g_dotood[(size_t)m * N + n];
            if (s < best) { best = s; bi = n; }
        }
        g_near[k * M + m] = bi;
        g_dnear[k * M + m] = delta[bi];
    }
}

// ---------------------------------------------------------------------------
// Per-class GEMM:  rot = R[k] (768x768) @ Xdiff (768xM), fused column-sumsq.
// 128x128 CTA tile, 16x16 threads, 8x8 microtile, k-tile 16.
__global__ __launch_bounds__(256) void abl_ood_gemm(const float* __restrict__ ood,
                                                    const float* __restrict__ cent,
                                                    int M) {
    int k = blockIdx.z;
    int rowBase = blockIdx.y * 128;
    int colBase = blockIdx.x * 128;
    const float* A = g_R + (size_t)k * DD * DD;

    __shared__ float sA[128][17];
    __shared__ float sB[16][132];
    __shared__ int snear[128];
    __shared__ float scol[16][128];

    int t = threadIdx.x;
    int tx = t & 15, ty = t >> 4;

    if (t < 128) {
        int m = colBase + t;
        if (m >= M) m = M - 1;
        snear[t] = g_near[k * M + m];
    }
    float acc[8][8];
#pragma unroll
    for (int r = 0; r < 8; r++)
#pragma unroll
        for (int c = 0; c < 8; c++) acc[r][c] = 0.f;
    __syncthreads();

    for (int j0 = 0; j0 < DD; j0 += 16) {
#pragma unroll
        for (int e = 0; e < 8; e++) {
            int ii = (t >> 4) + 16 * e;
            sA[ii][tx] = A[(size_t)(rowBase + ii) * DD + j0 + tx];
        }
#pragma unroll
        for (int e = 0; e < 8; e++) {
            int mm = (t >> 4) + 16 * e;
            int m = colBase + mm;
            if (m >= M) m = M - 1;
            int nb = snear[mm];
            sB[tx][mm] = ood[(size_t)m * DD + j0 + tx] - cent[(size_t)nb * DD + j0 + tx];
        }
        __syncthreads();
#pragma unroll
        for (int kk = 0; kk < 16; kk++) {
            float a[8], b[8];
#pragma unroll
            for (int r = 0; r < 8; r++) a[r] = sA[ty + 16 * r][kk];
#pragma unroll
            for (int c = 0; c < 8; c++) b[c] = sB[kk][tx + 16 * c];
#pragma unroll
            for (int r = 0; r < 8; r++)
#pragma unroll
                for (int c = 0; c < 8; c++) acc[r][c] += a[r] * b[c];
        }
        __syncthreads();
    }

    // per-column sum of squares within the CTA tile
#pragma unroll
    for (int c = 0; c < 8; c++) {
        float s = 0.f;
#pragma unroll
        for (int r = 0; r < 8; r++) s += acc[r][c] * acc[r][c];
        scol[ty][tx + 16 * c] = s;
    }
    __syncthreads();
    if (t < 128) {
        float s = 0.f;
#pragma unroll
        for (int y = 0; y < 16; y++) s += scol[y][t];
        int m = colBase + t;
        if (m < M) atomicAdd(&g_euc2ood[k * M + m], s);
    }
}

// ---------------------------------------------------------------------------
// In-dist: per-sample matvec ||R[cls] (pooled - c)||^2. One block per sample.
__global__ void abl_indist(const float* __restrict__ pooled,
                           const float* __restrict__ cent,
                           const int* __restrict__ blab) {
    int b = blockIdx.x;
    __shared__ float sx[DD];
    __shared__ float swr[8];
    int bid = g_ballin[b];
    for (int j = threadIdx.x; j < DD; j += 256)
        sx[j] = pooled[(size_t)b * DD + j] - cent[(size_t)bid * DD + j];
    __syncthreads();
    int cls = blab[bid];
    const float* A = g_R + (size_t)cls * DD * DD;
    int w = threadIdx.x >> 5, lane = threadIdx.x & 31;
    float wsum = 0.f;
    for (int i = w; i < DD; i += 8) {
        const float* row = A + (size_t)i * DD;
        float p = 0.f;
        for (int j = lane; j < DD; j += 32) p += row[j] * sx[j];
        for (int o = 16; o; o >>= 1) p += __shfl_down_sync(0xffffffffu, p, o);
        if (lane == 0) wsum += p * p;
    }
    if (lane == 0) swr[w] = wsum;
    __syncthreads();
    if (threadIdx.x == 0) {
        float s = 0.f;
        for (int i = 0; i < 8; i++) s += swr[i];
        g_eucin2[b] = s;
    }
}

// ---------------------------------------------------------------------------
__global__ void abl_finalize(float* __restrict__ out, int B, int M, int K, int out_size) {
    __shared__ float sred[256];
    int t = threadIdx.x;

    float pl = 0.f, pn = 0.f, nn = 0.f;
    for (int b = t; b < B; b += 256) {
        float e = sqrtf(g_eucin2[b]);
        float d = g_din[b];
        pl += (d > e) ? expf(e - d) : (e - d);
        if (e > d) pn += 1.f;
        if (e < d) nn += 1.f;
    }
    float ns = 0.f;
    for (int m = t; m < M; m += 256) {
        float s = 0.f;
        for (int k = 0; k < K; k++) {
            float e = sqrtf(g_euc2ood[k * M + m]);
            float d = g_dnear[k * M + m];
            s += (d > e) ? (d - e + BETA_C) : BETA_C * expf(d - e);
        }
        ns += s;
    }

    float vals[4] = {pl, pn, nn, ns};
    float red[4];
    for (int v = 0; v < 4; v++) {
        sred[t] = vals[v];
        __syncthreads();
        for (int s2 = 128; s2 > 0; s2 >>= 1) {
            if (t < s2) sred[t] += sred[t + s2];
            __syncthreads();
        }
        red[v] = sred[0];
        __syncthreads();
    }
    if (t == 0) {
        float pos_mean = red[0] / (float)B;
        float neg_mean = red[3] / (float)M;
        if (out_size > 0) out[0] = pos_mean;
        if (out_size > 1) out[1] = neg_mean;
        if (out_size > 2) out[2] = red[1];
        if (out_size > 3) out[3] = red[2];
        if (out_size > 4) out[4] = pos_mean + neg_mean;
    }
}

// ---------------------------------------------------------------------------
extern "C" void kernel_launch(void* const* d_in, const int* in_sizes, int n_in,
                              void* d_out, int out_size) {
    const float* pooled = (const float*)d_in[0];
    const float* ood    = (const float*)d_in[1];
    const float* cent   = (const float*)d_in[2];
    const float* delta  = (const float*)d_in[3];
    const float* L      = (const float*)d_in[4];
    const float* U      = (const float*)d_in[5];
    const float* Ddm    = (const float*)d_in[6];
    const int*   labels = (const int*)d_in[7];
    const int*   blab   = (const int*)d_in[8];

    int B = in_sizes[0] / DD;
    int M = in_sizes[1] / DD;
    int N = in_sizes[3];
    int K = in_sizes[6] / DD;
    int NTRI = in_sizes[4] / K;

    if (B > MAXB) B = MAXB;
    if (M > MAXM) M = MAXM;
    if (N > MAXN) N = MAXN;
    if (K > MAXK) K = MAXK;

    int ntiles = (DD / 32) * (DD / 32 + 1) / 2;   // 300

    abl_zero_cnt<<<1, 256>>>(K);
    abl_fill_clist<<<(N + 255) / 256, 256>>>(blab, N);
    abl_build_R<<<dim3(ntiles, K), 256>>>(L, U, Ddm, NTRI);
    abl_c2<<<N, 128>>>(cent);
    abl_dot_nt<<<dim3((N + 63) / 64, (B + 63) / 64), 256>>>(pooled, cent, B, N, 0);
    abl_dot_nt<<<dim3((N + 63) / 64, (M + 63) / 64), 256>>>(ood, cent, M, N, 1);
    abl_assign_in<<<(B + 255) / 256, 256>>>(labels, delta, B, N);
    abl_nearest_ood<<<K, 256>>>(delta, M, N);
    abl_zero_euc2<<<(K * M + 255) / 256, 256>>>(K * M);
    abl_ood_gemm<<<dim3((M + 127) / 128, DD / 128, K), 256>>>(ood, cent, M);
    abl_indist<<<B, 256>>>(pooled, cent, blab);
    abl_finalize<<<1, 256>>>((float*)d_out, B, M, K, out_size);
}

// round 2
// speedup vs baseline: 1.0460x; 1.0460x over previous
#include <cuda_runtime.h>
#include <math.h>

#define DD   768
#define MAXK 150
#define MAXN 1500
#define MAXB 256
#define MAXM 256
#define BETA_C 0.1f

// ---- scratch (static device globals; no allocation) ----
__device__ float g_R[(size_t)MAXK * DD * DD];      // 354 MB rotate matrices
__device__ float g_c2[MAXN];                        // centroid squared norms
__device__ float g_dotin[MAXB * MAXN];              // pooled . cent^T
__device__ float g_dotood[MAXM * MAXN];             // ood    . cent^T
__device__ int   g_cnt[MAXK];                       // balls per class
__device__ int   g_clist[MAXK * MAXN];              // class -> ball list
__device__ int   g_ballin[MAXB];                    // nearest same-class ball
__device__ float g_din[MAXB];
__device__ int   g_near[MAXK * MAXM];               // nearest class-k ball per ood sample
__device__ float g_dnear[MAXK * MAXM];
__device__ float g_euc2ood[MAXK * MAXM];            // accumulated ||R(o-c)||^2
__device__ float g_eucin2[MAXB];

// ---------------------------------------------------------------------------
__global__ void abl_zero_cnt(int K) {
    int t = threadIdx.x;
    if (t < K) g_cnt[t] = 0;
}

__global__ void abl_zero_euc2(int total) {
    int i = blockIdx.x * blockDim.x + threadIdx.x;
    if (i < total) g_euc2ood[i] = 0.f;
}

__global__ void abl_fill_clist(const int* __restrict__ blab, int N) {
    int n = blockIdx.x * blockDim.x + threadIdx.x;
    if (n >= N) return;
    int k = blab[n];
    int pos = atomicAdd(&g_cnt[k], 1);
    g_clist[k * MAXN + pos] = n;
}

// ---------------------------------------------------------------------------
// Build R[k] from packed L (strict lower), U (strict upper via transpose), Dd.
__global__ void abl_build_R(const float* __restrict__ L, const float* __restrict__ U,
                            const float* __restrict__ Ddm, int NTRI) {
    int k = blockIdx.y;
    int tidx = blockIdx.x;
    int ti = 0;
    while ((ti + 1) * (ti + 2) / 2 <= tidx) ti++;
    int tj = tidx - ti * (ti + 1) / 2;

    const float* Lk = L + (size_t)k * NTRI;
    const float* Uk = U + (size_t)k * NTRI;
    float* Rk = g_R + (size_t)k * DD * DD;

    __shared__ float su[32][33];
    int tx = threadIdx.x & 31, ty = threadIdx.x >> 5;

#pragma unroll
    for (int s = 0; s < 4; s++) {
        int ry = ty + 8 * s;
        int r = ti * 32 + ry, c = tj * 32 + tx;
        if (r > c) {
            size_t p = (size_t)r * (r - 1) / 2 + c;
            Rk[(size_t)r * DD + c] = Lk[p];
            su[ry][tx] = Uk[p];
        } else if (r == c) {
            Rk[(size_t)r * DD + c] = Ddm[(size_t)k * DD + r];
        }
    }
    __syncthreads();
#pragma unroll
    for (int s = 0; s < 4; s++) {
        int ry = ty + 8 * s;
        int ro = tj * 32 + ry, co = ti * 32 + tx;   // R[ro][co] = U_packed(co, ro)
        if (co > ro) Rk[(size_t)ro * DD + co] = su[tx][ry];
    }
}

// ---------------------------------------------------------------------------
// centroid squared norms
__global__ void abl_c2(const float* __restrict__ cent) {
    int n = blockIdx.x;
    __shared__ float sr[128];
    float s = 0.f;
    for (int j = threadIdx.x; j < DD; j += 128) {
        float v = cent[(size_t)n * DD + j];
        s += v * v;
    }
    sr[threadIdx.x] = s;
    __syncthreads();
    for (int k = 64; k > 0; k >>= 1) {
        if (threadIdx.x < k) sr[threadIdx.x] += sr[threadIdx.x + k];
        __syncthreads();
    }
    if (threadIdx.x == 0) g_c2[n] = sr[0];
}

// ---------------------------------------------------------------------------
// C[m][n] = A[m,:].B[n,:]  (NT).  64x64 tiles, 16x16 threads, 4x4 microtile.
__global__ __launch_bounds__(256) void abl_dot_nt(const float* __restrict__ A,
                                                  const float* __restrict__ Bm,
                                                  int Ma, int Nb, int which) {
    float* C = which ? g_dotood : g_dotin;
    __shared__ float sA[16][65];
    __shared__ float sB[16][65];
    int n0 = blockIdx.x * 64, m0 = blockIdx.y * 64;
    int t = threadIdx.x, tx = t & 15, ty = t >> 4;
    float acc[4][4];
#pragma unroll
    for (int r = 0; r < 4; r++)
#pragma unroll
        for (int c = 0; c < 4; c++) acc[r][c] = 0.f;

    for (int j0 = 0; j0 < DD; j0 += 16) {
#pragma unroll
        for (int e = 0; e < 4; e++) {
            int mm = (t >> 4) + 16 * e;
            int m = m0 + mm;
            sA[tx][mm] = (m < Ma) ? A[(size_t)m * DD + j0 + tx] : 0.f;
        }
#pragma unroll
        for (int e = 0; e < 4; e++) {
            int nn = (t >> 4) + 16 * e;
            int n = n0 + nn;
            sB[tx][nn] = (n < Nb) ? Bm[(size_t)n * DD + j0 + tx] : 0.f;
        }
        __syncthreads();
#pragma unroll
        for (int kk = 0; kk < 16; kk++) {
            float a[4], b[4];
#pragma unroll
            for (int r = 0; r < 4; r++) a[r] = sA[kk][ty * 4 + r];
#pragma unroll
            for (int c = 0; c < 4; c++) b[c] = sB[kk][tx * 4 + c];
#pragma unroll
            for (int r = 0; r < 4; r++)
#pragma unroll
                for (int c = 0; c < 4; c++) acc[r][c] += a[r] * b[c];
        }
        __syncthreads();
    }
#pragma unroll
    for (int r = 0; r < 4; r++) {
        int m = m0 + ty * 4 + r;
        if (m >= Ma) continue;
#pragma unroll
        for (int c = 0; c < 4; c++) {
            int n = n0 + tx * 4 + c;
            if (n < Nb) C[(size_t)m * Nb + n] = acc[r][c];
        }
    }
}

// ---------------------------------------------------------------------------
// nearest same-class ball per in-dist sample (argmin of ||c||^2 - 2 a.c)
__global__ void abl_assign_in(const int* __restrict__ labels,
                              const float* __restrict__ delta, int B, int N) {
    int b = blockIdx.x * blockDim.x + threadIdx.x;
    if (b >= B) return;
    int lab = labels[b];
    int cnt = g_cnt[lab];
    float best = 3.4e38f;
    int bi = 0;
    for (int i = 0; i < cnt; i++) {
        int n = g_clist[lab * MAXN + i];
        float s = g_c2[n] - 2.f * g_dotin[(size_t)b * N + n];
        if (s < best) { best = s; bi = n; }
    }
    g_ballin[b] = bi;
    g_din[b] = delta[bi];
}

// nearest class-k ball per ood sample
__global__ void abl_nearest_ood(const float* __restrict__ delta, int M, int N) {
    int k = blockIdx.x;
    int cnt = g_cnt[k];
    for (int m = threadIdx.x; m < M; m += blockDim.x) {
        float best = 3.4e38f;
        int bi = 0;
        for (int i = 0; i < cnt; i++) {
            int n = g_clist[k * MAXN + i];
            float s = g_c2[n] - 2.f * g_dotood[(size_t)m * N + n];
            if (s < best) { best = s; bi = n; }
        }
        g_near[k * M + m] = bi;
        g_dnear[k * M + m] = delta[bi];
    }
}

// ---------------------------------------------------------------------------
// Per-class GEMM with packed fp32x2 (FFMA2):
//   rot = R[k] (768x768) @ Xdiff (768xM), fused column-sumsq.
// 128x128 CTA tile, 256 threads.
// Thread (tx,ty) owns rows 8*ty..8*ty+7 (4 packed row-pairs) and cols
// tx+16*cc, cc=0..7. B is stored duplicated ({b,b}) in smem so the packed
// operand comes straight from one LDS.64; A row-pairs come from LDS.128.
__global__ __launch_bounds__(256, 2) void abl_ood_gemm(const float* __restrict__ ood,
                                                       const float* __restrict__ cent,
                                                       int M) {
    int k = blockIdx.z;
    int rowBase = blockIdx.y * 128;
    int colBase = blockIdx.x * 128;
    const float* A = g_R + (size_t)k * DD * DD;

    __shared__ __align__(16) float sA[16][132];   // [kk][row]
    __shared__ __align__(16) float sB[16][258];   // [kk][2*col] duplicated
    __shared__ int snear[128];
    __shared__ float scol[16][128];

    int t = threadIdx.x;
    int tx = t & 15, ty = t >> 4;

    if (t < 128) {
        int m = colBase + t;
        if (m >= M) m = M - 1;
        snear[t] = g_near[k * M + m];
    }

    unsigned long long acc[4][8];
#pragma unroll
    for (int q = 0; q < 4; q++)
#pragma unroll
        for (int c = 0; c < 8; c++) acc[q][c] = 0ull;
    __syncthreads();

    for (int j0 = 0; j0 < DD; j0 += 16) {
        // A tile: 128 rows x 16 k-cols, stored [kk][row]
#pragma unroll
        for (int e = 0; e < 8; e++) {
            int ii = ty + 16 * e;
            sA[tx][ii] = A[(size_t)(rowBase + ii) * DD + j0 + tx];
        }
        // B tile (duplicated): col mm, value ood - cent
#pragma unroll
        for (int e = 0; e < 8; e++) {
            int mm = ty + 16 * e;
            int m = colBase + mm;
            if (m >= M) m = M - 1;
            int nb = snear[mm];
            float b = ood[(size_t)m * DD + j0 + tx] - cent[(size_t)nb * DD + j0 + tx];
            unsigned long long bb;
            asm("mov.b64 %0, {%1, %1};" : "=l"(bb) : "f"(b));
            *reinterpret_cast<unsigned long long*>(&sB[tx][2 * mm]) = bb;
        }
        __syncthreads();
#pragma unroll
        for (int kk = 0; kk < 16; kk++) {
            unsigned long long a01, a23, a45, a67;
            {
                const ulonglong2* pa =
                    reinterpret_cast<const ulonglong2*>(&sA[kk][8 * ty]);
                ulonglong2 v0 = pa[0];        // rows 8ty..8ty+3
                a01 = v0.x; a23 = v0.y;
                ulonglong2 v1 = pa[1];        // rows 8ty+4..8ty+7
                a45 = v1.x; a67 = v1.y;
            }
#pragma unroll
            for (int cc = 0; cc < 8; cc++) {
                unsigned long long bv =
                    *reinterpret_cast<const unsigned long long*>(&sB[kk][2 * (tx + 16 * cc)]);
                asm("fma.rn.f32x2 %0, %1, %2, %0;" : "+l"(acc[0][cc]) : "l"(a01), "l"(bv));
                asm("fma.rn.f32x2 %0, %1, %2, %0;" : "+l"(acc[1][cc]) : "l"(a23), "l"(bv));
                asm("fma.rn.f32x2 %0, %1, %2, %0;" : "+l"(acc[2][cc]) : "l"(a45), "l"(bv));
                asm("fma.rn.f32x2 %0, %1, %2, %0;" : "+l"(acc[3][cc]) : "l"(a67), "l"(bv));
            }
        }
        __syncthreads();
    }

    // per-column sum of squares within the CTA tile
#pragma unroll
    for (int cc = 0; cc < 8; cc++) {
        float s = 0.f;
#pragma unroll
        for (int q = 0; q < 4; q++) {
            float lo = __uint_as_float((unsigned)(acc[q][cc] & 0xffffffffull));
            float hi = __uint_as_float((unsigned)(acc[q][cc] >> 32));
            s += lo * lo + hi * hi;
        }
        scol[ty][tx + 16 * cc] = s;
    }
    __syncthreads();
    if (t < 128) {
        float s = 0.f;
#pragma unroll
        for (int y = 0; y < 16; y++) s += scol[y][t];
        int m = colBase + t;
        if (m < M) atomicAdd(&g_euc2ood[k * M + m], s);
    }
}

// ---------------------------------------------------------------------------
// In-dist: per-sample matvec ||R[cls] (pooled - c)||^2. One block per sample.
__global__ void abl_indist(const float* __restrict__ pooled,
                           const float* __restrict__ cent,
                           const int* __restrict__ blab) {
    int b = blockIdx.x;
    __shared__ float sx[DD];
    __shared__ float swr[8];
    int bid = g_ballin[b];
    for (int j = threadIdx.x; j < DD; j += 256)
        sx[j] = pooled[(size_t)b * DD + j] - cent[(size_t)bid * DD + j];
    __syncthreads();
    int cls = blab[bid];
    const float* A = g_R + (size_t)cls * DD * DD;
    int w = threadIdx.x >> 5, lane = threadIdx.x & 31;
    float wsum = 0.f;
    for (int i = w; i < DD; i += 8) {
        const float4* row = reinterpret_cast<const float4*>(A + (size_t)i * DD);
        float p = 0.f;
        for (int j = lane; j < DD / 4; j += 32) {
            float4 r4 = row[j];
            p += r4.x * sx[4 * j] + r4.y * sx[4 * j + 1] +
                 r4.z * sx[4 * j + 2] + r4.w * sx[4 * j + 3];
        }
        for (int o = 16; o; o >>= 1) p += __shfl_down_sync(0xffffffffu, p, o);
        if (lane == 0) wsum += p * p;
    }
    if (lane == 0) swr[w] = wsum;
    __syncthreads();
    if (threadIdx.x == 0) {
        float s = 0.f;
        for (int i = 0; i < 8; i++) s += swr[i];
        g_eucin2[b] = s;
    }
}

// ---------------------------------------------------------------------------
__global__ void abl_finalize(float* __restrict__ out, int B, int M, int K, int out_size) {
    __shared__ float sred[256];
    int t = threadIdx.x;

    float pl = 0.f, pn = 0.f, nn = 0.f;
    for (int b = t; b < B; b += 256) {
        float e = sqrtf(g_eucin2[b]);
        float d = g_din[b];
        pl += (d > e) ? expf(e - d) : (e - d);
        if (e > d) pn += 1.f;
        if (e < d) nn += 1.f;
    }
    float ns = 0.f;
    for (int m = t; m < M; m += 256) {
        float s = 0.f;
        for (int k = 0; k < K; k++) {
            float e = sqrtf(g_euc2ood[k * M + m]);
            float d = g_dnear[k * M + m];
            s += (d > e) ? (d - e + BETA_C) : BETA_C * expf(d - e);
        }
        ns += s;
    }

    float vals[4] = {pl, pn, nn, ns};
    float red[4];
    for (int v = 0; v < 4; v++) {
        sred[t] = vals[v];
        __syncthreads();
        for (int s2 = 128; s2 > 0; s2 >>= 1) {
            if (t < s2) sred[t] += sred[t + s2];
            __syncthreads();
        }
        red[v] = sred[0];
        __syncthreads();
    }
    if (t == 0) {
        float pos_mean = red[0] / (float)B;
        float neg_mean = red[3] / (float)M;
        if (out_size > 0) out[0] = pos_mean;
        if (out_size > 1) out[1] = neg_mean;
        if (out_size > 2) out[2] = red[1];
        if (out_size > 3) out[3] = red[2];
        if (out_size > 4) out[4] = pos_mean + neg_mean;
    }
}

// ---------------------------------------------------------------------------
extern "C" void kernel_launch(void* const* d_in, const int* in_sizes, int n_in,
                              void* d_out, int out_size) {
    const float* pooled = (const float*)d_in[0];
    const float* ood    = (const float*)d_in[1];
    const float* cent   = (const float*)d_in[2];
    const float* delta  = (const float*)d_in[3];
    const float* L      = (const float*)d_in[4];
    const float* U      = (const float*)d_in[5];
    const float* Ddm    = (const float*)d_in[6];
    const int*   labels = (const int*)d_in[7];
    const int*   blab   = (const int*)d_in[8];

    int B = in_sizes[0] / DD;
    int M = in_sizes[1] / DD;
    int N = in_sizes[3];
    int K = in_sizes[6] / DD;
    int NTRI = in_sizes[4] / K;

    if (B > MAXB) B = MAXB;
    if (M > MAXM) M = MAXM;
    if (N > MAXN) N = MAXN;
    if (K > MAXK) K = MAXK;

    int ntiles = (DD / 32) * (DD / 32 + 1) / 2;   // 300

    abl_zero_cnt<<<1, 256>>>(K);
    abl_fill_clist<<<(N + 255) / 256, 256>>>(blab, N);
    abl_build_R<<<dim3(ntiles, K), 256>>>(L, U, Ddm, NTRI);
    abl_c2<<<N, 128>>>(cent);
    abl_dot_nt<<<dim3((N + 63) / 64, (B + 63) / 64), 256>>>(pooled, cent, B, N, 0);
    abl_dot_nt<<<dim3((N + 63) / 64, (M + 63) / 64), 256>>>(ood, cent, M, N, 1);
    abl_assign_in<<<(B + 255) / 256, 256>>>(labels, delta, B, N);
    abl_nearest_ood<<<K, 256>>>(delta, M, N);
    abl_zero_euc2<<<(K * M + 255) / 256, 256>>>(K * M);
    abl_ood_gemm<<<dim3((M + 127) / 128, DD / 128, K), 256>>>(ood, cent, M);
    abl_indist<<<B, 256>>>(pooled, cent, blab);
    abl_finalize<<<1, 256>>>((float*)d_out, B, M, K, out_size);
}

// round 8
// speedup vs baseline: 1.3568x; 1.2972x over previous
#include <cuda_runtime.h>
#include <math.h>
#include <stdint.h>

#define DD   768
#define MAXK 150
#define MAXN 1500
#define MAXB 256
#define MAXM 256
#define BETA_C 0.1f

// ---- scratch (static device globals; no allocation) ----
__device__ float g_R[(size_t)MAXK * DD * DD];      // 354 MB rotate matrices
__device__ float g_c2[MAXN];
__device__ float g_dotin[MAXB * MAXN];
__device__ float g_dotood[MAXM * MAXN];
__device__ int   g_cnt[MAXK];
__device__ int   g_clist[MAXK * MAXN];
__device__ int   g_ballin[MAXB];
__device__ float g_din[MAXB];
__device__ int   g_near[MAXK * MAXM];
__device__ float g_dnear[MAXK * MAXM];
__device__ float g_euc2ood[MAXK * MAXM];
__device__ float g_eucin2[MAXB];

// ======================= small setup kernels ===============================
__global__ void abl_zero_cnt(int K) {
    int t = threadIdx.x;
    if (t < K) g_cnt[t] = 0;
}
__global__ void abl_zero_euc2(int total) {
    int i = blockIdx.x * blockDim.x + threadIdx.x;
    if (i < total) g_euc2ood[i] = 0.f;
}
__global__ void abl_fill_clist(const int* __restrict__ blab, int N) {
    int n = blockIdx.x * blockDim.x + threadIdx.x;
    if (n >= N) return;
    int k = blab[n];
    int pos = atomicAdd(&g_cnt[k], 1);
    g_clist[k * MAXN + pos] = n;
}

__global__ void abl_build_R(const float* __restrict__ L, const float* __restrict__ U,
                            const float* __restrict__ Ddm, int NTRI) {
    int k = blockIdx.y;
    int tidx = blockIdx.x;
    int ti = 0;
    while ((ti + 1) * (ti + 2) / 2 <= tidx) ti++;
    int tj = tidx - ti * (ti + 1) / 2;

    const float* Lk = L + (size_t)k * NTRI;
    const float* Uk = U + (size_t)k * NTRI;
    float* Rk = g_R + (size_t)k * DD * DD;

    __shared__ float su[32][33];
    int tx = threadIdx.x & 31, ty = threadIdx.x >> 5;
#pragma unroll
    for (int s = 0; s < 4; s++) {
        int ry = ty + 8 * s;
        int r = ti * 32 + ry, c = tj * 32 + tx;
        if (r > c) {
            size_t p = (size_t)r * (r - 1) / 2 + c;
            Rk[(size_t)r * DD + c] = Lk[p];
            su[ry][tx] = Uk[p];
        } else if (r == c) {
            Rk[(size_t)r * DD + c] = Ddm[(size_t)k * DD + r];
        }
    }
    __syncthreads();
#pragma unroll
    for (int s = 0; s < 4; s++) {
        int ry = ty + 8 * s;
        int ro = tj * 32 + ry, co = ti * 32 + tx;
        if (co > ro) Rk[(size_t)ro * DD + co] = su[tx][ry];
    }
}

__global__ void abl_c2(const float* __restrict__ cent) {
    int n = blockIdx.x;
    __shared__ float sr[128];
    float s = 0.f;
    for (int j = threadIdx.x; j < DD; j += 128) {
        float v = cent[(size_t)n * DD + j];
        s += v * v;
    }
    sr[threadIdx.x] = s;
    __syncthreads();
    for (int k = 64; k > 0; k >>= 1) {
        if (threadIdx.x < k) sr[threadIdx.x] += sr[threadIdx.x + k];
        __syncthreads();
    }
    if (threadIdx.x == 0) g_c2[n] = sr[0];
}

__global__ __launch_bounds__(256) void abl_dot_nt(const float* __restrict__ A,
                                                  const float* __restrict__ Bm,
                                                  int Ma, int Nb, int which) {
    float* C = which ? g_dotood : g_dotin;
    __shared__ float sA[16][65];
    __shared__ float sB[16][65];
    int n0 = blockIdx.x * 64, m0 = blockIdx.y * 64;
    int t = threadIdx.x, tx = t & 15, ty = t >> 4;
    float acc[4][4];
#pragma unroll
    for (int r = 0; r < 4; r++)
#pragma unroll
        for (int c = 0; c < 4; c++) acc[r][c] = 0.f;

    for (int j0 = 0; j0 < DD; j0 += 16) {
#pragma unroll
        for (int e = 0; e < 4; e++) {
            int mm = (t >> 4) + 16 * e;
            int m = m0 + mm;
            sA[tx][mm] = (m < Ma) ? A[(size_t)m * DD + j0 + tx] : 0.f;
        }
#pragma unroll
        for (int e = 0; e < 4; e++) {
            int nn = (t >> 4) + 16 * e;
            int n = n0 + nn;
            sB[tx][nn] = (n < Nb) ? Bm[(size_t)n * DD + j0 + tx] : 0.f;
        }
        __syncthreads();
#pragma unroll
        for (int kk = 0; kk < 16; kk++) {
            float a[4], b[4];
#pragma unroll
            for (int r = 0; r < 4; r++) a[r] = sA[kk][ty * 4 + r];
#pragma unroll
            for (int c = 0; c < 4; c++) b[c] = sB[kk][tx * 4 + c];
#pragma unroll
            for (int r = 0; r < 4; r++)
#pragma unroll
                for (int c = 0; c < 4; c++) acc[r][c] += a[r] * b[c];
        }
        __syncthreads();
    }
#pragma unroll
    for (int r = 0; r < 4; r++) {
        int m = m0 + ty * 4 + r;
        if (m >= Ma) continue;
#pragma unroll
        for (int c = 0; c < 4; c++) {
            int n = n0 + tx * 4 + c;
            if (n < Nb) C[(size_t)m * Nb + n] = acc[r][c];
        }
    }
}

__global__ void abl_assign_in(const int* __restrict__ labels,
                              const float* __restrict__ delta, int B, int N) {
    int b = blockIdx.x * blockDim.x + threadIdx.x;
    if (b >= B) return;
    int lab = labels[b];
    int cnt = g_cnt[lab];
    float best = 3.4e38f;
    int bi = 0;
    for (int i = 0; i < cnt; i++) {
        int n = g_clist[lab * MAXN + i];
        float s = g_c2[n] - 2.f * g_dotin[(size_t)b * N + n];
        if (s < best) { best = s; bi = n; }
    }
    g_ballin[b] = bi;
    g_din[b] = delta[bi];
}

__global__ void abl_nearest_ood(const float* __restrict__ delta, int M, int N) {
    int k = blockIdx.x;
    int cnt = g_cnt[k];
    for (int m = threadIdx.x; m < M; m += blockDim.x) {
        float best = 3.4e38f;
        int bi = 0;
        for (int i = 0; i < cnt; i++) {
            int n = g_clist[k * MAXN + i];
            float s = g_c2[n] - 2.f * g_dotood[(size_t)m * N + n];
            if (s < best) { best = s; bi = n; }
        }
        g_near[k * M + m] = bi;
        g_dnear[k * M + m] = delta[bi];
    }
}

// ================= mma.sync tf32 OOD GEMM (3xTF32) =========================
// D[128,128] tile of  R_k(768x768) @ Xdiff^T(768x256), fused column sumsq.
// 256 threads = 8 warps (2 x 4), warp tile 64x32, k-chunk 32, 3xTF32 passes:
//   D += Ah.Bh + Al.Bh + Ah.Bl  (element error ~2^-21)
#define KC   32
#define LDSW 36                 // smem row stride in floats (conflict-free frags)
#define TILE_FLOATS (128 * LDSW)
#define SMEM_MMA_BYTES (4 * TILE_FLOATS * 4)   // sAh, sAl, sBh, sBl = 73728 B

__device__ __forceinline__ uint32_t tf32_of(float x) {
    uint32_t h;
    asm("cvt.rna.tf32.f32 %0, %1;" : "=r"(h) : "f"(x));
    return h;
}
__device__ __forceinline__ void split_tf32(float x, uint32_t& hi, uint32_t& lo) {
    hi = tf32_of(x);
    lo = tf32_of(x - __uint_as_float(hi));
}
__device__ __forceinline__ void mma_tf32(float* d, const uint32_t* a, const uint32_t* b) {
    asm volatile(
        "mma.sync.aligned.m16n8k8.row.col.f32.tf32.tf32.f32 "
        "{%0,%1,%2,%3}, {%4,%5,%6,%7}, {%8,%9}, {%0,%1,%2,%3};"
        : "+f"(d[0]), "+f"(d[1]), "+f"(d[2]), "+f"(d[3])
        : "r"(a[0]), "r"(a[1]), "r"(a[2]), "r"(a[3]), "r"(b[0]), "r"(b[1]));
}

__global__ __launch_bounds__(256, 2) void abl_ood_mma(const float* __restrict__ ood,
                                                      const float* __restrict__ cent,
                                                      int M) {
    extern __shared__ float sm[];
    float* sAh = sm;
    float* sAl = sm + TILE_FLOATS;
    float* sBh = sm + 2 * TILE_FLOATS;
    float* sBl = sm + 3 * TILE_FLOATS;
    __shared__ int snear[128];
    __shared__ float scol[128];

    int k = blockIdx.z;
    int rowBase = blockIdx.y * 128;
    int colBase = blockIdx.x * 128;
    const float* A = g_R + (size_t)k * DD * DD;

    int t = threadIdx.x, wid = t >> 5, lane = t & 31;
    int wm = (wid >> 2) * 64;        // warp m offset (0 or 64)
    int wn = (wid & 3) * 32;         // warp n offset (0,32,64,96)
    int gid = lane >> 2, tig = lane & 3;

    if (t < 128) {
        int m = colBase + t;
        if (m >= M) m = M - 1;
        snear[t] = g_near[k * M + m];
        scol[t] = 0.f;
    }
    __syncthreads();

    float acc[4][4][4];
#pragma unroll
    for (int mt = 0; mt < 4; mt++)
#pragma unroll
        for (int nt = 0; nt < 4; nt++)
#pragma unroll
            for (int r = 0; r < 4; r++) acc[mt][nt][r] = 0.f;

    for (int c = 0; c < DD / KC; c++) {
        int j0 = c * KC;
        // ---- load A tile (128x32) ----
#pragma unroll
        for (int e = 0; e < 4; e++) {
            int idx = t + 256 * e;
            int row = idx >> 3, c4 = idx & 7;
            float4 v = *(const float4*)(A + (size_t)(rowBase + row) * DD + j0 + c4 * 4);
            uint32_t h0, l0, h1, l1, h2, l2, h3, l3;
            split_tf32(v.x, h0, l0); split_tf32(v.y, h1, l1);
            split_tf32(v.z, h2, l2); split_tf32(v.w, h3, l3);
            int off = row * LDSW + c4 * 4;
            *(uint4*)(sAh + off) = make_uint4(h0, h1, h2, h3);
            *(uint4*)(sAl + off) = make_uint4(l0, l1, l2, l3);
        }
        // ---- load B tile (128 samples x 32), gathered diff ----
#pragma unroll
        for (int e = 0; e < 4; e++) {
            int idx = t + 256 * e;
            int row = idx >> 3, c4 = idx & 7;
            int m = colBase + row;
            if (m >= M) m = M - 1;
            int nb = snear[row];
            float4 o = *(const float4*)(ood + (size_t)m * DD + j0 + c4 * 4);
            float4 ce = *(const float4*)(cent + (size_t)nb * DD + j0 + c4 * 4);
            float4 v = make_float4(o.x - ce.x, o.y - ce.y, o.z - ce.z, o.w - ce.w);
            uint32_t h0, l0, h1, l1, h2, l2, h3, l3;
            split_tf32(v.x, h0, l0); split_tf32(v.y, h1, l1);
            split_tf32(v.z, h2, l2); split_tf32(v.w, h3, l3);
            int off = row * LDSW + c4 * 4;
            *(uint4*)(sBh + off) = make_uint4(h0, h1, h2, h3);
            *(uint4*)(sBl + off) = make_uint4(l0, l1, l2, l3);
        }
        __syncthreads();

#pragma unroll
        for (int kt = 0; kt < 4; kt++) {
            int kb = kt * 8;
            uint32_t ah[4][4], al[4][4], bh[4][2], bl[4][2];
#pragma unroll
            for (int mt = 0; mt < 4; mt++) {
                int r0 = (wm + mt * 16 + gid) * LDSW + kb + tig;
                int r1 = r0 + 8 * LDSW;
                ah[mt][0] = __float_as_uint(sAh[r0]);
                ah[mt][1] = __float_as_uint(sAh[r1]);
                ah[mt][2] = __float_as_uint(sAh[r0 + 4]);
                ah[mt][3] = __float_as_uint(sAh[r1 + 4]);
                al[mt][0] = __float_as_uint(sAl[r0]);
                al[mt][1] = __float_as_uint(sAl[r1]);
                al[mt][2] = __float_as_uint(sAl[r0 + 4]);
                al[mt][3] = __float_as_uint(sAl[r1 + 4]);
            }
#pragma unroll
            for (int nt = 0; nt < 4; nt++) {
                int n0 = (wn + nt * 8 + gid) * LDSW + kb + tig;
                bh[nt][0] = __float_as_uint(sBh[n0]);
                bh[nt][1] = __float_as_uint(sBh[n0 + 4]);
                bl[nt][0] = __float_as_uint(sBl[n0]);
                bl[nt][1] = __float_as_uint(sBl[n0 + 4]);
            }
#pragma unroll
            for (int mt = 0; mt < 4; mt++)
#pragma unroll
                for (int nt = 0; nt < 4; nt++) {
                    mma_tf32(acc[mt][nt], ah[mt], bh[nt]);
                    mma_tf32(acc[mt][nt], al[mt], bh[nt]);
                    mma_tf32(acc[mt][nt], ah[mt], bl[nt]);
                }
        }
        __syncthreads();
    }

    // ---- epilogue: column sum of squares ----
    // reg r of tile (mt,nt): row = wm+16mt+gid (+8 if r>=2), col = wn+8nt+2tig+(r&1)
#pragma unroll
    for (int nt = 0; nt < 4; nt++) {
        float s0 = 0.f, s1 = 0.f;
#pragma unroll
        for (int mt = 0; mt < 4; mt++) {
            s0 += acc[mt][nt][0] * acc[mt][nt][0] + acc[mt][nt][2] * acc[mt][nt][2];
            s1 += acc[mt][nt][1] * acc[mt][nt][1] + acc[mt][nt][3] * acc[mt][nt][3];
        }
#pragma unroll
        for (int o = 16; o >= 4; o >>= 1) {
            s0 += __shfl_down_sync(0xffffffffu, s0, o);
            s1 += __shfl_down_sync(0xffffffffu, s1, o);
        }
        if (lane < 4) {
            atomicAdd(&scol[wn + nt * 8 + 2 * lane], s0);
            atomicAdd(&scol[wn + nt * 8 + 2 * lane + 1], s1);
        }
    }
    __syncthreads();
    if (t < 128) {
        int col = colBase + t;
        if (col < M) atomicAdd(&g_euc2ood[k * M + col], scol[t]);
    }
}

// ======================= in-dist matvec + finalize =========================
__global__ void abl_indist(const float* __restrict__ pooled,
                           const float* __restrict__ cent,
                           const int* __restrict__ blab) {
    int b = blockIdx.x;
    __shared__ float sx[DD];
    __shared__ float swr[8];
    int bid = g_ballin[b];
    for (int j = threadIdx.x; j < DD; j += 256)
        sx[j] = pooled[(size_t)b * DD + j] - cent[(size_t)bid * DD + j];
    __syncthreads();
    int cls = blab[bid];
    const float* A = g_R + (size_t)cls * DD * DD;
    int w = threadIdx.x >> 5, lane = threadIdx.x & 31;
    float wsum = 0.f;
    for (int i = w; i < DD; i += 8) {
        const float4* row = reinterpret_cast<const float4*>(A + (size_t)i * DD);
        float p = 0.f;
        for (int j = lane; j < DD / 4; j += 32) {
            float4 r4 = row[j];
            p += r4.x * sx[4 * j] + r4.y * sx[4 * j + 1] +
                 r4.z * sx[4 * j + 2] + r4.w * sx[4 * j + 3];
        }
        for (int o = 16; o; o >>= 1) p += __shfl_down_sync(0xffffffffu, p, o);
        if (lane == 0) wsum += p * p;
    }
    if (lane == 0) swr[w] = wsum;
    __syncthreads();
    if (threadIdx.x == 0) {
        float s = 0.f;
        for (int i = 0; i < 8; i++) s += swr[i];
        g_eucin2[b] = s;
    }
}

__global__ void abl_finalize(float* __restrict__ out, int B, int M, int K, int out_size) {
    __shared__ float sred[256];
    int t = threadIdx.x;

    float pl = 0.f, pn = 0.f, nn = 0.f;
    for (int b = t; b < B; b += 256) {
        float e = sqrtf(g_eucin2[b]);
        float d = g_din[b];
        pl += (d > e) ? expf(e - d) : (e - d);
        if (e > d) pn += 1.f;
        if (e < d) nn += 1.f;
    }
    float ns = 0.f;
    for (int m = t; m < M; m += 256) {
        float s = 0.f;
        for (int k = 0; k < K; k++) {
            float e = sqrtf(g_euc2ood[k * M + m]);
            float d = g_dnear[k * M + m];
            s += (d > e) ? (d - e + BETA_C) : BETA_C * expf(d - e);
        }
        ns += s;
    }

    float vals[4] = {pl, pn, nn, ns};
    float red[4];
    for (int v = 0; v < 4; v++) {
        sred[t] = vals[v];
        __syncthreads();
        for (int s2 = 128; s2 > 0; s2 >>= 1) {
            if (t < s2) sred[t] += sred[t + s2];
            __syncthreads();
        }
        red[v] = sred[0];
        __syncthreads();
    }
    if (t == 0) {
        float pos_mean = red[0] / (float)B;
        float neg_mean = red[3] / (float)M;
        if (out_size > 0) out[0] = pos_mean;
        if (out_size > 1) out[1] = neg_mean;
        if (out_size > 2) out[2] = red[1];
        if (out_size > 3) out[3] = red[2];
        if (out_size > 4) out[4] = pos_mean + neg_mean;
    }
}

// ---------------------------------------------------------------------------
extern "C" void kernel_launch(void* const* d_in, const int* in_sizes, int n_in,
                              void* d_out, int out_size) {
    const float* pooled = (const float*)d_in[0];
    const float* ood    = (const float*)d_in[1];
    const float* cent   = (const float*)d_in[2];
    const float* delta  = (const float*)d_in[3];
    const float* L      = (const float*)d_in[4];
    const float* U      = (const float*)d_in[5];
    const float* Ddm    = (const float*)d_in[6];
    const int*   labels = (const int*)d_in[7];
    const int*   blab   = (const int*)d_in[8];

    int B = in_sizes[0] / DD;
    int M = in_sizes[1] / DD;
    int N = in_sizes[3];
    int K = in_sizes[6] / DD;
    int NTRI = in_sizes[4] / K;

    if (B > MAXB) B = MAXB;
    if (M > MAXM) M = MAXM;
    if (N > MAXN) N = MAXN;
    if (K > MAXK) K = MAXK;

    int ntiles = (DD / 32) * (DD / 32 + 1) / 2;   // 300

    cudaFuncSetAttribute(abl_ood_mma, cudaFuncAttributeMaxDynamicSharedMemorySize,
                         SMEM_MMA_BYTES);

    abl_zero_cnt<<<1, 256>>>(K);
    abl_fill_clist<<<(N + 255) / 256, 256>>>(blab, N);
    abl_build_R<<<dim3(ntiles, K), 256>>>(L, U, Ddm, NTRI);
    abl_c2<<<N, 128>>>(cent);
    abl_dot_nt<<<dim3((N + 63) / 64, (B + 63) / 64), 256>>>(pooled, cent, B, N, 0);
    abl_dot_nt<<<dim3((N + 63) / 64, (M + 63) / 64), 256>>>(ood, cent, M, N, 1);
    abl_assign_in<<<(B + 255) / 256, 256>>>(labels, delta, B, N);
    abl_nearest_ood<<<K, 256>>>(delta, M, N);
    abl_zero_euc2<<<(K * M + 255) / 256, 256>>>(K * M);
    abl_ood_mma<<<dim3((M + 127) / 128, DD / 128, K), 256, SMEM_MMA_BYTES>>>(ood, cent, M);
    abl_indist<<<B, 256>>>(pooled, cent, blab);
    abl_finalize<<<1, 256>>>((float*)d_out, B, M, K, out_size);
}